// round 1
// baseline (speedup 1.0000x reference)
#include <cuda_runtime.h>
#include <math.h>

#define C_CLS 1000
#define CP    1024      // C padded to 64-multiple
#define AD    512       // ATT_DIM == IMG_DIM
#define HD    256       // H
#define NMAX  131072

// ---------------- scratch (device globals; zero-initialized at load) --------
__device__ float g_attr[CP * AD];     // padded attributes
__device__ float g_p[CP * HD];        // p / pn (in-place normalize)
__device__ float g_d[CP * CP];        // cosine matrices
__device__ float g_A[CP * CP];        // softmax outputs
__device__ float g_enc[CP * AD];      // encoded attrs
__device__ float g_q[CP * HD];        // q / qn
__device__ float g_mean[C_CLS * AD];  // per-class means
__device__ float g_protos[CP * AD];   // gathered protos (pad rows stay 0)
__device__ int   g_counts[C_CLS];
__device__ int   g_offsets[C_CLS];
__device__ int   g_cursor[C_CLS];
__device__ int   g_sorted[NMAX];

// ---------------- reductions ------------------------------------------------
__device__ __forceinline__ float warpSum(float v) {
#pragma unroll
    for (int o = 16; o; o >>= 1) v += __shfl_xor_sync(0xffffffffu, v, o);
    return v;
}
__device__ __forceinline__ float warpMax(float v) {
#pragma unroll
    for (int o = 16; o; o >>= 1) v = fmaxf(v, __shfl_xor_sync(0xffffffffu, v, o));
    return v;
}
__device__ __forceinline__ float blockSum(float v, float* sh) {
    int t = threadIdx.x, lane = t & 31, w = t >> 5, nw = blockDim.x >> 5;
    v = warpSum(v);
    if (!lane) sh[w] = v;
    __syncthreads();
    if (w == 0) {
        float x = (lane < nw) ? sh[lane] : 0.f;
        x = warpSum(x);
        if (!lane) sh[0] = x;
    }
    __syncthreads();
    float r = sh[0];
    __syncthreads();
    return r;
}
__device__ __forceinline__ float blockMax(float v, float* sh) {
    int t = threadIdx.x, lane = t & 31, w = t >> 5, nw = blockDim.x >> 5;
    v = warpMax(v);
    if (!lane) sh[w] = v;
    __syncthreads();
    if (w == 0) {
        float x = (lane < nw) ? sh[lane] : -1e30f;
        x = warpMax(x);
        if (!lane) sh[0] = x;
    }
    __syncthreads();
    float r = sh[0];
    __syncthreads();
    return r;
}

// ---------------- proto pipeline --------------------------------------------
__global__ void zero_counts_k() {
    int i = blockIdx.x * blockDim.x + threadIdx.x;
    if (i < C_CLS) { g_counts[i] = 0; g_cursor[i] = 0; }
}
__global__ void hist_k(const int* __restrict__ labels, int n) {
    int i = blockIdx.x * blockDim.x + threadIdx.x;
    if (i < n) atomicAdd(&g_counts[labels[i]], 1);
}
__global__ void scan_k() {
    __shared__ int s[1024];
    int t = threadIdx.x;
    int c = (t < C_CLS) ? g_counts[t] : 0;
    s[t] = c;
    __syncthreads();
    for (int off = 1; off < 1024; off <<= 1) {
        int v = (t >= off) ? s[t - off] : 0;
        __syncthreads();
        s[t] += v;
        __syncthreads();
    }
    if (t < C_CLS) g_offsets[t] = s[t] - c;   // exclusive
}
__global__ void scatter_k(const int* __restrict__ labels, int n) {
    int i = blockIdx.x * blockDim.x + threadIdx.x;
    if (i < n) {
        int l = labels[i];
        int pos = g_offsets[l] + atomicAdd(&g_cursor[l], 1);
        g_sorted[pos] = i;
    }
}
__global__ __launch_bounds__(128) void class_mean_k(const float* __restrict__ img) {
    int c = blockIdx.x;
    int t = threadIdx.x;                 // owns float4 column t (4 floats)
    int cnt = g_counts[c], off = g_offsets[c];
    __shared__ int idx[256];
    int lim = cnt < 256 ? cnt : 256;
    for (int j = t; j < lim; j += 128) idx[j] = g_sorted[off + j];
    __syncthreads();
    float4 acc = make_float4(0.f, 0.f, 0.f, 0.f);
    int j = 0;
    for (; j + 4 <= lim; j += 4) {
        int r0 = idx[j], r1 = idx[j + 1], r2 = idx[j + 2], r3 = idx[j + 3];
        float4 a = ((const float4*)(img + (size_t)r0 * AD))[t];
        float4 b = ((const float4*)(img + (size_t)r1 * AD))[t];
        float4 d = ((const float4*)(img + (size_t)r2 * AD))[t];
        float4 e = ((const float4*)(img + (size_t)r3 * AD))[t];
        acc.x += a.x + b.x + d.x + e.x;
        acc.y += a.y + b.y + d.y + e.y;
        acc.z += a.z + b.z + d.z + e.z;
        acc.w += a.w + b.w + d.w + e.w;
    }
    for (; j < lim; j++) {
        float4 a = ((const float4*)(img + (size_t)idx[j] * AD))[t];
        acc.x += a.x; acc.y += a.y; acc.z += a.z; acc.w += a.w;
    }
    for (j = 256; j < cnt; j++) {        // statistically never (E[cnt]~100)
        int r = g_sorted[off + j];
        float4 a = ((const float4*)(img + (size_t)r * AD))[t];
        acc.x += a.x; acc.y += a.y; acc.z += a.z; acc.w += a.w;
    }
    float inv = cnt > 0 ? 1.f / (float)cnt : 0.f;
    float4 o = make_float4(acc.x * inv, acc.y * inv, acc.z * inv, acc.w * inv);
    ((float4*)(g_mean + (size_t)c * AD))[t] = o;
}
__global__ void gather_protos_k(const int* __restrict__ tpl) {
    int i = blockIdx.x, t = threadIdx.x;
    float4 v = make_float4(0.f, 0.f, 0.f, 0.f);
    if (i < C_CLS) {
        int s = tpl[i];
        v = ((const float4*)(g_mean + (size_t)s * AD))[t];
    }
    ((float4*)(g_protos + (size_t)i * AD))[t] = v;
}
__global__ void pad_attr_k(const float* __restrict__ attrs) {
    int i = blockIdx.x, t = threadIdx.x;
    float4 v = make_float4(0.f, 0.f, 0.f, 0.f);
    if (i < C_CLS) v = ((const float4*)(attrs + (size_t)i * AD))[t];
    ((float4*)(g_attr + (size_t)i * AD))[t] = v;
}

// ---------------- SGEMM: C[M,N] = A[M,K] @ B (NT: B is [N,K]) ---------------
template <bool NT>
__global__ __launch_bounds__(256) void sgemm(const float* __restrict__ A,
                                             const float* __restrict__ B,
                                             float* __restrict__ Cc,
                                             int M, int N, int K, int mstore) {
    __shared__ float As[16][68];
    __shared__ float Bs[16][68];
    const int m0 = blockIdx.y * 64, n0 = blockIdx.x * 64;
    const int tid = threadIdx.x;
    const int tx = tid & 15, ty = tid >> 4;
    const int lr = tid >> 2;          // 0..63
    const int lk = (tid & 3) * 4;     // 0,4,8,12

    float acc[4][4] = {};
    for (int k0 = 0; k0 < K; k0 += 16) {
        float4 av = *(const float4*)(A + (size_t)(m0 + lr) * K + k0 + lk);
        As[lk + 0][lr] = av.x; As[lk + 1][lr] = av.y;
        As[lk + 2][lr] = av.z; As[lk + 3][lr] = av.w;
        if (NT) {
            float4 bv = *(const float4*)(B + (size_t)(n0 + lr) * K + k0 + lk);
            Bs[lk + 0][lr] = bv.x; Bs[lk + 1][lr] = bv.y;
            Bs[lk + 2][lr] = bv.z; Bs[lk + 3][lr] = bv.w;
        } else {
            int kr = tid >> 4;            // 0..15
            int nc = (tid & 15) * 4;      // 0..60
            float4 bv = *(const float4*)(B + (size_t)(k0 + kr) * N + n0 + nc);
            *(float4*)&Bs[kr][nc] = bv;
        }
        __syncthreads();
#pragma unroll
        for (int kk = 0; kk < 16; kk++) {
            float4 a = *(const float4*)&As[kk][ty * 4];
            float4 b = *(const float4*)&Bs[kk][tx * 4];
            acc[0][0] += a.x * b.x; acc[0][1] += a.x * b.y;
            acc[0][2] += a.x * b.z; acc[0][3] += a.x * b.w;
            acc[1][0] += a.y * b.x; acc[1][1] += a.y * b.y;
            acc[1][2] += a.y * b.z; acc[1][3] += a.y * b.w;
            acc[2][0] += a.z * b.x; acc[2][1] += a.z * b.y;
            acc[2][2] += a.z * b.z; acc[2][3] += a.z * b.w;
            acc[3][0] += a.w * b.x; acc[3][1] += a.w * b.y;
            acc[3][2] += a.w * b.z; acc[3][3] += a.w * b.w;
        }
        __syncthreads();
    }
#pragma unroll
    for (int i = 0; i < 4; i++) {
        int m = m0 + ty * 4 + i;
        if (m < mstore) {
            float4 o = make_float4(acc[i][0], acc[i][1], acc[i][2], acc[i][3]);
            *(float4*)(Cc + (size_t)m * N + n0 + tx * 4) = o;
        }
    }
}

// ---------------- row normalize & masked softmax ----------------------------
__global__ __launch_bounds__(256) void rownorm_k(float* __restrict__ P) {
    __shared__ float sh[32];
    int r = blockIdx.x;
    float* row = P + (size_t)r * HD;
    float x = row[threadIdx.x];
    float ss = blockSum(x * x, sh);
    row[threadIdx.x] = x * rsqrtf(fmaxf(ss, 1e-30f));
}

__global__ __launch_bounds__(256) void masked_softmax_k(const float* __restrict__ D,
                                                        float* __restrict__ O) {
    __shared__ float sh[32];
    int r = blockIdx.x;
    const float* din = D + (size_t)r * CP;
    float* o = O + (size_t)r * CP;
    int t = threadIdx.x;
    if (r >= C_CLS) {
        for (int c = t; c < CP; c += 256) o[c] = 0.f;
        return;
    }
    float v[4];
    float mx = -1e30f;
#pragma unroll
    for (int j = 0; j < 4; j++) {
        int c = t + j * 256;
        float x = (c < C_CLS) ? din[c] : -1e30f;
        v[j] = x;
        if (x > 0.5f) mx = fmaxf(mx, x);
    }
    mx = blockMax(mx, sh);
    float m10 = mx * 10.f;
    float e[4];
    float s = 0.f;
#pragma unroll
    for (int j = 0; j < 4; j++) {
        e[j] = (v[j] > 0.5f) ? expf(v[j] * 10.f - m10) : 0.f;
        s += e[j];
    }
    s = blockSum(s, sh);
    float inv = 1.f / s;
#pragma unroll
    for (int j = 0; j < 4; j++) {
        int c = t + j * 256;
        o[c] = (c < C_CLS) ? e[j] * inv : 0.f;
    }
}

// ---------------- launch -----------------------------------------------------
static float* symf(const void* p) { return (float*)p; }

extern "C" void kernel_launch(void* const* d_in, const int* in_sizes, int n_in,
                              void* d_out, int out_size) {
    const float* img   = (const float*)d_in[0];
    const float* attrs = (const float*)d_in[1];
    const float* att_g = (const float*)d_in[2];
    const float* att_h = (const float*)d_in[3];
    const int*   labels = (const int*)d_in[4];
    const int*   tpl    = (const int*)d_in[5];
    float* out = (float*)d_out;
    int N = in_sizes[4];
    (void)n_in; (void)out_size;

    void *p_attr, *p_p, *p_d, *p_A, *p_enc, *p_q, *p_protos;
    cudaGetSymbolAddress(&p_attr, g_attr);
    cudaGetSymbolAddress(&p_p, g_p);
    cudaGetSymbolAddress(&p_d, g_d);
    cudaGetSymbolAddress(&p_A, g_A);
    cudaGetSymbolAddress(&p_enc, g_enc);
    cudaGetSymbolAddress(&p_q, g_q);
    cudaGetSymbolAddress(&p_protos, g_protos);
    float* A_attr  = symf(p_attr);
    float* A_p     = symf(p_p);
    float* A_d     = symf(p_d);
    float* A_A     = symf(p_A);
    float* A_enc   = symf(p_enc);
    float* A_q     = symf(p_q);
    float* A_prot  = symf(p_protos);

    // --- proto pipeline (counting sort + per-class mean) ---
    zero_counts_k<<<4, 256>>>();
    hist_k<<<(N + 255) / 256, 256>>>(labels, N);
    scan_k<<<1, 1024>>>();
    scatter_k<<<(N + 255) / 256, 256>>>(labels, N);
    class_mean_k<<<C_CLS, 128>>>(img);
    gather_protos_k<<<CP, 128>>>(tpl);

    // --- attribute encoding chain ---
    pad_attr_k<<<CP, 128>>>(attrs);
    // p = attr_pad @ att_h : [1024,512]x[512,256]
    sgemm<false><<<dim3(HD / 64, CP / 64), 256>>>(A_attr, att_h, A_p, CP, HD, AD, CP);
    rownorm_k<<<CP, HD>>>(A_p);
    // d = pn @ pn^T
    sgemm<true><<<dim3(CP / 64, CP / 64), 256>>>(A_p, A_p, A_d, CP, CP, HD, CP);
    masked_softmax_k<<<CP, 256>>>(A_d, A_A);
    // enc = A1 @ attr_pad : [1024,1024]x[1024,512]
    sgemm<false><<<dim3(AD / 64, CP / 64), 256>>>(A_A, A_attr, A_enc, CP, AD, CP, CP);
    // q = enc @ att_g : [1024,512]x[512,256]
    sgemm<false><<<dim3(HD / 64, CP / 64), 256>>>(A_enc, att_g, A_q, CP, HD, AD, CP);
    rownorm_k<<<CP, HD>>>(A_q);
    // d2 = qn @ qn^T
    sgemm<true><<<dim3(CP / 64, CP / 64), 256>>>(A_q, A_q, A_d, CP, CP, HD, CP);
    masked_softmax_k<<<CP, 256>>>(A_d, A_A);
    // out = attention @ protos : [1024,1024]x[1024,512], store rows < 1000
    sgemm<false><<<dim3(AD / 64, CP / 64), 256>>>(A_A, A_prot, out, CP, AD, CP, C_CLS);
}